// round 2
// baseline (speedup 1.0000x reference)
#include <cuda_runtime.h>
#include <math.h>

#define BB 4
#define TT 4096
#define DD 1024
#define HH 8
#define DH 128
#define MM (BB*TT)          // 16384 rows
#define NEGV (-1000000.0f)

// ---------------- scratch (static device allocations; no cudaMalloc) ----------------
__device__ float g_xn[(size_t)MM * DD];      // 64 MB  LayerNorm output
__device__ float g_q [(size_t)MM * DD];      // 64 MB  raw q
__device__ float g_k [(size_t)MM * DD];      // 64 MB  raw k (+NEG on padded rows)
__device__ float g_v [(size_t)MM * DD];      // 64 MB  masked v
__device__ float g_att[BB * HH * DH * DH];   // 2 MB   unnormalized att (atomic accum)
__device__ float g_Z [BB * DD];              // time-softmax denominators

// ---------------- LayerNorm ----------------
__global__ __launch_bounds__(256) void ln_kernel(const float* __restrict__ x,
                                                 const float* __restrict__ gamma,
                                                 const float* __restrict__ beta) {
    __shared__ float red[18];
    int row = blockIdx.x;
    int tid = threadIdx.x;
    const float4* xr = (const float4*)(x + (size_t)row * DD);
    float4 v = xr[tid];
    float s = v.x + v.y + v.z + v.w;
    #pragma unroll
    for (int o = 16; o; o >>= 1) s += __shfl_xor_sync(0xffffffffu, s, o);
    if ((tid & 31) == 0) red[tid >> 5] = s;
    __syncthreads();
    if (tid < 32) {
        float t = (tid < 8) ? red[tid] : 0.f;
        #pragma unroll
        for (int o = 4; o; o >>= 1) t += __shfl_xor_sync(0xffffffffu, t, o);
        if (tid == 0) red[16] = t;
    }
    __syncthreads();
    float mu = red[16] * (1.0f / DD);
    float d0 = v.x - mu, d1 = v.y - mu, d2 = v.z - mu, d3 = v.w - mu;
    float sq = d0*d0 + d1*d1 + d2*d2 + d3*d3;
    #pragma unroll
    for (int o = 16; o; o >>= 1) sq += __shfl_xor_sync(0xffffffffu, sq, o);
    if ((tid & 31) == 0) red[tid >> 5] = sq;
    __syncthreads();
    if (tid < 32) {
        float t = (tid < 8) ? red[tid] : 0.f;
        #pragma unroll
        for (int o = 4; o; o >>= 1) t += __shfl_xor_sync(0xffffffffu, t, o);
        if (tid == 0) red[17] = t;
    }
    __syncthreads();
    float inv = rsqrtf(red[17] * (1.0f / DD) + 1e-5f);
    float4 g  = ((const float4*)gamma)[tid];
    float4 bt = ((const float4*)beta)[tid];
    float4 o4;
    o4.x = d0 * inv * g.x + bt.x;
    o4.y = d1 * inv * g.y + bt.y;
    o4.z = d2 * inv * g.z + bt.z;
    o4.w = d3 * inv * g.w + bt.w;
    ((float4*)(g_xn + (size_t)row * DD))[tid] = o4;
}

// ---------------- QKV GEMM: C = xn @ W + b (+k-mask / *v-mask) ----------------
// 128x128 tile, BK=16, 256 threads, 8x8 microtile per thread.
__global__ __launch_bounds__(256) void qkv_gemm_kernel(const float* __restrict__ W,
                                                       const float* __restrict__ bias,
                                                       const float* __restrict__ mask,
                                                       int mode) {
    __shared__ float As[16][132];   // [k][m]
    __shared__ float Bs[16][132];   // [k][n]
    int tid = threadIdx.x;
    int m0 = blockIdx.y * 128;
    int n0 = blockIdx.x * 128;
    int tx = tid & 15, ty = tid >> 4;
    int aRow = tid >> 2;            // 0..63
    int aCol = (tid & 3) << 2;      // 0,4,8,12
    int bRow = tid >> 5;            // 0..7
    int bCol = (tid & 31) << 2;
    const float* A = g_xn;
    float* C = (mode == 0) ? g_q : (mode == 1) ? g_k : g_v;

    float acc[8][8];
    #pragma unroll
    for (int i = 0; i < 8; i++)
        #pragma unroll
        for (int j = 0; j < 8; j++) acc[i][j] = 0.f;

    for (int k0 = 0; k0 < DD; k0 += 16) {
        float4 a0 = *(const float4*)(A + (size_t)(m0 + aRow)      * DD + k0 + aCol);
        float4 a1 = *(const float4*)(A + (size_t)(m0 + aRow + 64) * DD + k0 + aCol);
        float4 b0 = *(const float4*)(W + (size_t)(k0 + bRow)     * DD + n0 + bCol);
        float4 b1 = *(const float4*)(W + (size_t)(k0 + bRow + 8) * DD + n0 + bCol);
        As[aCol+0][aRow] = a0.x; As[aCol+1][aRow] = a0.y;
        As[aCol+2][aRow] = a0.z; As[aCol+3][aRow] = a0.w;
        As[aCol+0][aRow+64] = a1.x; As[aCol+1][aRow+64] = a1.y;
        As[aCol+2][aRow+64] = a1.z; As[aCol+3][aRow+64] = a1.w;
        *(float4*)&Bs[bRow][bCol]   = b0;
        *(float4*)&Bs[bRow+8][bCol] = b1;
        __syncthreads();
        #pragma unroll
        for (int kk = 0; kk < 16; kk++) {
            float a[8], b[8];
            *(float4*)(a)   = *(const float4*)&As[kk][ty*8];
            *(float4*)(a+4) = *(const float4*)&As[kk][ty*8+4];
            *(float4*)(b)   = *(const float4*)&Bs[kk][tx*8];
            *(float4*)(b+4) = *(const float4*)&Bs[kk][tx*8+4];
            #pragma unroll
            for (int i = 0; i < 8; i++)
                #pragma unroll
                for (int j = 0; j < 8; j++)
                    acc[i][j] += a[i] * b[j];
        }
        __syncthreads();
    }
    float bb[8];
    *(float4*)(bb)   = *(const float4*)(bias + n0 + tx*8);
    *(float4*)(bb+4) = *(const float4*)(bias + n0 + tx*8 + 4);
    #pragma unroll
    for (int i = 0; i < 8; i++) {
        int m = m0 + ty*8 + i;
        float mk = mask[m];
        float addk = (mode == 1) ? (1.0f - mk) * NEGV : 0.0f;
        float mulv = (mode == 2) ? mk : 1.0f;
        float4 o0, o1;
        o0.x = (acc[i][0] + bb[0] + addk) * mulv;
        o0.y = (acc[i][1] + bb[1] + addk) * mulv;
        o0.z = (acc[i][2] + bb[2] + addk) * mulv;
        o0.w = (acc[i][3] + bb[3] + addk) * mulv;
        o1.x = (acc[i][4] + bb[4] + addk) * mulv;
        o1.y = (acc[i][5] + bb[5] + addk) * mulv;
        o1.z = (acc[i][6] + bb[6] + addk) * mulv;
        o1.w = (acc[i][7] + bb[7] + addk) * mulv;
        float* cp = C + (size_t)m * DD + n0 + tx*8;
        *(float4*)cp     = o0;
        *(float4*)(cp+4) = o1;
    }
}

// ---------------- zero att + Z ----------------
__global__ void zero_kernel() {
    int i = blockIdx.x * 256 + threadIdx.x;
    if (i < BB*HH*DH*DH) g_att[i] = 0.f;
    if (i < BB*DD)       g_Z[i]   = 0.f;
}

// ---------------- att = exp(K)^T V  (split-K over T, atomic accumulate), Z = col-sums of exp(K)
#define TSPLIT 16
__global__ __launch_bounds__(256) void att_kernel() {
    __shared__ float ks[16][132];
    __shared__ float vs[16][132];
    int tid = threadIdx.x;
    int bh = blockIdx.x;
    int b = bh >> 3, h = bh & 7;
    int n_start = blockIdx.y * (TT / TSPLIT);     // 256 timesteps per split
    const float* kp = g_k + ((size_t)b * TT) * DD + h * DH;
    const float* vp = g_v + ((size_t)b * TT) * DD + h * DH;
    int tx = tid & 15, ty = tid >> 4;
    int lr = tid >> 4;            // chunk row 0..15
    int lc = (tid & 15) * 8;      // 8 floats per thread per row
    float acc[8][8];
    #pragma unroll
    for (int i = 0; i < 8; i++)
        #pragma unroll
        for (int j = 0; j < 8; j++) acc[i][j] = 0.f;
    float zacc = 0.f;

    for (int c = 0; c < TT / TSPLIT; c += 16) {
        size_t n = (size_t)(n_start + c + lr);
        const float* kr = kp + n * DD + lc;
        const float* vr = vp + n * DD + lc;
        float4 k0 = *(const float4*)kr, k1 = *(const float4*)(kr + 4);
        float4 v0 = *(const float4*)vr, v1 = *(const float4*)(vr + 4);
        float4 e0, e1;
        e0.x = __expf(k0.x); e0.y = __expf(k0.y); e0.z = __expf(k0.z); e0.w = __expf(k0.w);
        e1.x = __expf(k1.x); e1.y = __expf(k1.y); e1.z = __expf(k1.z); e1.w = __expf(k1.w);
        *(float4*)&ks[lr][lc]   = e0;
        *(float4*)&ks[lr][lc+4] = e1;
        *(float4*)&vs[lr][lc]   = v0;
        *(float4*)&vs[lr][lc+4] = v1;
        __syncthreads();
        if (tid < 128) {
            #pragma unroll
            for (int r = 0; r < 16; r++) zacc += ks[r][tid];
        }
        #pragma unroll
        for (int kk = 0; kk < 16; kk++) {
            float a[8], bf[8];
            *(float4*)(a)    = *(const float4*)&ks[kk][ty*8];
            *(float4*)(a+4)  = *(const float4*)&ks[kk][ty*8+4];
            *(float4*)(bf)   = *(const float4*)&vs[kk][tx*8];
            *(float4*)(bf+4) = *(const float4*)&vs[kk][tx*8+4];
            #pragma unroll
            for (int i = 0; i < 8; i++)
                #pragma unroll
                for (int j = 0; j < 8; j++)
                    acc[i][j] += a[i] * bf[j];
        }
        __syncthreads();
    }
    if (tid < 128) atomicAdd(&g_Z[b * DD + h * DH + tid], zacc);
    float* attp = g_att + (size_t)bh * DH * DH;
    #pragma unroll
    for (int i = 0; i < 8; i++)
        #pragma unroll
        for (int j = 0; j < 8; j++)
            atomicAdd(&attp[(ty*8+i)*DH + tx*8+j], acc[i][j]);
}

// ---------------- y = softmax_row(q) @ (att / Z) ; out = x + y ----------------
__global__ __launch_bounds__(256) void y_kernel(const float* __restrict__ x,
                                                float* __restrict__ out) {
    extern __shared__ float sm[];
    float* att_s = sm;                 // 128 * 132
    float* qs    = sm + 128 * 132;     // 128 * 132
    int tid = threadIdx.x;
    int t0 = blockIdx.x * 128;
    int h = blockIdx.y;
    int b = blockIdx.z;
    int bh = b * HH + h;

    // att load with Z normalization
    {
        const float* attp = g_att + (size_t)bh * DH * DH;
        int rr = tid >> 1;
        int part = (tid & 1) * 64;
        float zinv = 1.0f / g_Z[b * DD + h * DH + rr];
        #pragma unroll
        for (int c = 0; c < 64; c += 4) {
            float4 av = *(const float4*)(attp + rr * DH + part + c);
            av.x *= zinv; av.y *= zinv; av.z *= zinv; av.w *= zinv;
            *(float4*)&att_s[rr * 132 + part + c] = av;
        }
    }
    // q row-softmax (over Dh=128, contiguous): one warp per row
    {
        int warp = tid >> 5, lane = tid & 31;
        for (int r = warp; r < 128; r += 8) {
            const float* qrow = g_q + ((size_t)(b * TT + t0 + r)) * DD + h * DH + lane * 4;
            float4 qv = *(const float4*)qrow;
            float mx = fmaxf(fmaxf(qv.x, qv.y), fmaxf(qv.z, qv.w));
            #pragma unroll
            for (int o = 16; o; o >>= 1) mx = fmaxf(mx, __shfl_xor_sync(0xffffffffu, mx, o));
            float e0 = __expf(qv.x - mx), e1 = __expf(qv.y - mx);
            float e2 = __expf(qv.z - mx), e3 = __expf(qv.w - mx);
            float s = e0 + e1 + e2 + e3;
            #pragma unroll
            for (int o = 16; o; o >>= 1) s += __shfl_xor_sync(0xffffffffu, s, o);
            float inv = 1.0f / s;
            float4 o4 = { e0*inv, e1*inv, e2*inv, e3*inv };
            *(float4*)&qs[r * 132 + lane * 4] = o4;
        }
    }
    __syncthreads();

    int tx = tid & 15, ty = tid >> 4;
    float acc[8][8];
    #pragma unroll
    for (int i = 0; i < 8; i++)
        #pragma unroll
        for (int j = 0; j < 8; j++) acc[i][j] = 0.f;

    for (int kk = 0; kk < DH; kk++) {
        float a[8], bf[8];
        #pragma unroll
        for (int i = 0; i < 8; i++) a[i] = qs[(ty*8+i) * 132 + kk];
        *(float4*)(bf)   = *(const float4*)&att_s[kk * 132 + tx*8];
        *(float4*)(bf+4) = *(const float4*)&att_s[kk * 132 + tx*8 + 4];
        #pragma unroll
        for (int i = 0; i < 8; i++)
            #pragma unroll
            for (int j = 0; j < 8; j++)
                acc[i][j] += a[i] * bf[j];
    }
    #pragma unroll
    for (int i = 0; i < 8; i++) {
        size_t base = ((size_t)(b * TT + t0 + ty*8 + i)) * DD + h * DH + tx * 8;
        float4 x0 = *(const float4*)(x + base);
        float4 x1 = *(const float4*)(x + base + 4);
        float4 o0 = { x0.x + acc[i][0], x0.y + acc[i][1], x0.z + acc[i][2], x0.w + acc[i][3] };
        float4 o1 = { x1.x + acc[i][4], x1.y + acc[i][5], x1.z + acc[i][6], x1.w + acc[i][7] };
        *(float4*)(out + base)     = o0;
        *(float4*)(out + base + 4) = o1;
    }
}

// ---------------- launch ----------------
extern "C" void kernel_launch(void* const* d_in, const int* in_sizes, int n_in,
                              void* d_out, int out_size) {
    const float* x        = (const float*)d_in[0];
    const float* src_mask = (const float*)d_in[1];
    const float* Wq       = (const float*)d_in[2];
    const float* bq       = (const float*)d_in[3];
    const float* Wk       = (const float*)d_in[4];
    const float* bk       = (const float*)d_in[5];
    const float* Wv       = (const float*)d_in[6];
    const float* bv       = (const float*)d_in[7];
    const float* gamma    = (const float*)d_in[8];
    const float* beta     = (const float*)d_in[9];
    float* out = (float*)d_out;

    int ysmem = 2 * 128 * 132 * 4;
    cudaFuncSetAttribute(y_kernel, cudaFuncAttributeMaxDynamicSharedMemorySize, ysmem);

    ln_kernel<<<MM, 256>>>(x, gamma, beta);
    dim3 gg(DD / 128, MM / 128);
    qkv_gemm_kernel<<<gg, 256>>>(Wq, bq, src_mask, 0);
    qkv_gemm_kernel<<<gg, 256>>>(Wk, bk, src_mask, 1);
    qkv_gemm_kernel<<<gg, 256>>>(Wv, bv, src_mask, 2);
    zero_kernel<<<(BB*HH*DH*DH + 255) / 256, 256>>>();
    att_kernel<<<dim3(BB*HH, TSPLIT), 256>>>();
    y_kernel<<<dim3(TT/128, HH, BB), 256, ysmem>>>(x, out);
}

// round 6
// speedup vs baseline: 2.8548x; 2.8548x over previous
#include <cuda_runtime.h>
#include <cuda_bf16.h>
#include <math.h>
#include <cstdint>

#define BB 4
#define TT 4096
#define DD 1024
#define HH 8
#define DH 128
#define MM (BB*TT)          // 16384 rows
#define NEGV (-1000000.0f)

// ---------------- scratch (static device allocations; no cudaMalloc) ----------------
__device__ __nv_bfloat16 g_xnb[(size_t)MM * DD];        // 32 MB  LayerNorm output (bf16)
__device__ __nv_bfloat16 g_wbT[3][(size_t)DD * DD];     // 6 MB   W transposed to [N][K] bf16
__device__ float g_q [(size_t)MM * DD];                 // 64 MB  raw q
__device__ float g_k [(size_t)MM * DD];                 // 64 MB  raw k (+NEG on padded rows)
__device__ float g_v [(size_t)MM * DD];                 // 64 MB  masked v
__device__ float g_att[BB * HH * DH * DH];              // 2 MB   unnormalized att (atomic accum)
__device__ float g_Z [BB * DD];                         // time-softmax denominators

__device__ __forceinline__ uint32_t smem_u32(const void* p) {
    uint32_t a;
    asm("{ .reg .u64 t; cvta.to.shared.u64 t, %1; cvt.u32.u64 %0, t; }" : "=r"(a) : "l"(p));
    return a;
}

// ---------------- LayerNorm -> bf16 xn ----------------
__global__ __launch_bounds__(256) void ln_kernel(const float* __restrict__ x,
                                                 const float* __restrict__ gamma,
                                                 const float* __restrict__ beta) {
    __shared__ float red[18];
    int row = blockIdx.x;
    int tid = threadIdx.x;
    const float4* xr = (const float4*)(x + (size_t)row * DD);
    float4 v = xr[tid];
    float s = v.x + v.y + v.z + v.w;
    #pragma unroll
    for (int o = 16; o; o >>= 1) s += __shfl_xor_sync(0xffffffffu, s, o);
    if ((tid & 31) == 0) red[tid >> 5] = s;
    __syncthreads();
    if (tid < 32) {
        float t = (tid < 8) ? red[tid] : 0.f;
        #pragma unroll
        for (int o = 4; o; o >>= 1) t += __shfl_xor_sync(0xffffffffu, t, o);
        if (tid == 0) red[16] = t;
    }
    __syncthreads();
    float mu = red[16] * (1.0f / DD);
    float d0 = v.x - mu, d1 = v.y - mu, d2 = v.z - mu, d3 = v.w - mu;
    float sq = d0*d0 + d1*d1 + d2*d2 + d3*d3;
    #pragma unroll
    for (int o = 16; o; o >>= 1) sq += __shfl_xor_sync(0xffffffffu, sq, o);
    if ((tid & 31) == 0) red[tid >> 5] = sq;
    __syncthreads();
    if (tid < 32) {
        float t = (tid < 8) ? red[tid] : 0.f;
        #pragma unroll
        for (int o = 4; o; o >>= 1) t += __shfl_xor_sync(0xffffffffu, t, o);
        if (tid == 0) red[17] = t;
    }
    __syncthreads();
    float inv = rsqrtf(red[17] * (1.0f / DD) + 1e-5f);
    float4 g  = ((const float4*)gamma)[tid];
    float4 bt = ((const float4*)beta)[tid];
    float o0 = d0 * inv * g.x + bt.x;
    float o1 = d1 * inv * g.y + bt.y;
    float o2 = d2 * inv * g.z + bt.z;
    float o3 = d3 * inv * g.w + bt.w;
    __nv_bfloat162* xo = (__nv_bfloat162*)(g_xnb + (size_t)row * DD);
    xo[tid * 2]     = __floats2bfloat162_rn(o0, o1);
    xo[tid * 2 + 1] = __floats2bfloat162_rn(o2, o3);
}

// ---------------- W -> bf16 transposed [N][K] ----------------
__global__ void wconv_kernel(const float* __restrict__ Wq,
                             const float* __restrict__ Wk,
                             const float* __restrict__ Wv) {
    __shared__ float t[32][33];
    int z = blockIdx.z;
    const float* W = (z == 0) ? Wq : (z == 1) ? Wk : Wv;
    int k = blockIdx.y * 32 + threadIdx.y;
    int n = blockIdx.x * 32 + threadIdx.x;
    t[threadIdx.y][threadIdx.x] = W[(size_t)k * DD + n];
    __syncthreads();
    int n2 = blockIdx.x * 32 + threadIdx.y;
    int k2 = blockIdx.y * 32 + threadIdx.x;
    g_wbT[z][(size_t)n2 * DD + k2] = __float2bfloat16_rn(t[threadIdx.x][threadIdx.y]);
}

// ================= mma.sync bf16 QKV GEMM =================
// 128x128 tile, BK=32, 256 threads (8 warps), warp tile 64x32.
// SMEM rows padded to 40 bf16 (80B) -> ldmatrix conflict-free.
#define BK 32
#define APAD 40     // elements per padded row

__device__ __forceinline__ void ldsm_x4(uint32_t& r0, uint32_t& r1, uint32_t& r2, uint32_t& r3, uint32_t a) {
    asm volatile("ldmatrix.sync.aligned.m8n8.x4.shared.b16 {%0,%1,%2,%3}, [%4];"
                 : "=r"(r0), "=r"(r1), "=r"(r2), "=r"(r3) : "r"(a));
}
__device__ __forceinline__ void mma16816(float* d, uint32_t a0, uint32_t a1, uint32_t a2, uint32_t a3,
                                         uint32_t b0, uint32_t b1) {
    asm volatile("mma.sync.aligned.m16n8k16.row.col.f32.bf16.bf16.f32 "
                 "{%0,%1,%2,%3}, {%4,%5,%6,%7}, {%8,%9}, {%0,%1,%2,%3};"
                 : "+f"(d[0]), "+f"(d[1]), "+f"(d[2]), "+f"(d[3])
                 : "r"(a0), "r"(a1), "r"(a2), "r"(a3), "r"(b0), "r"(b1));
}
#define CP_ASYNC16(sm, gm) asm volatile("cp.async.cg.shared.global [%0], [%1], 16;" :: "r"(sm), "l"(gm))
#define CP_COMMIT()        asm volatile("cp.async.commit_group;" ::: "memory")

__global__ __launch_bounds__(256) void qkv_mma_kernel(
    const float* __restrict__ bq, const float* __restrict__ bk,
    const float* __restrict__ bv, const float* __restrict__ mask) {
    __shared__ __nv_bfloat16 As[2][128 * APAD];
    __shared__ __nv_bfloat16 Bs[2][128 * APAD];
    int tid = threadIdx.x;
    int wid = tid >> 5, lane = tid & 31;
    int mat = blockIdx.z;
    int m0 = blockIdx.y * 128, n0 = blockIdx.x * 128;
    const __nv_bfloat16* Ag = g_xnb + (size_t)m0 * DD;
    const __nv_bfloat16* Bg = g_wbT[mat] + (size_t)n0 * DD;
    float* C = (mat == 0) ? g_q : (mat == 1) ? g_k : g_v;
    const float* bias = (mat == 0) ? bq : (mat == 1) ? bk : bv;

    // loader slots: each row has 4 x 16B chunks; thread pair covers one row,
    // tid&1==0 -> chunks {0,2}, tid&1==1 -> chunks {1,3}
    int r0i = tid >> 1;                 // rows 0..127
    int u0 = (tid & 1);                 // chunk 0 or 1 (second chunk = +2)
    uint32_t sA = smem_u32(As), sB = smem_u32(Bs);
    uint32_t dstA0 = sA + (r0i * APAD + u0 * 8) * 2;
    uint32_t dstB0 = sB + (r0i * APAD + u0 * 8) * 2;
    const __nv_bfloat16* gA0 = Ag + (size_t)r0i * DD + u0 * 8;
    const __nv_bfloat16* gB0 = Bg + (size_t)r0i * DD + u0 * 8;
    const uint32_t bufAbytes = 128 * APAD * 2;

    // prefetch tile 0
    {
        CP_ASYNC16(dstA0, gA0);        CP_ASYNC16(dstA0 + 32, gA0 + 16);
        CP_ASYNC16(dstB0, gB0);        CP_ASYNC16(dstB0 + 32, gB0 + 16);
        CP_COMMIT();
    }

    int wr = wid >> 2, wc = wid & 3;    // warp 64-row group, 32-col group
    float acc[4][4][4];
    #pragma unroll
    for (int i = 0; i < 4; i++)
        #pragma unroll
        for (int j = 0; j < 4; j++)
            #pragma unroll
            for (int c = 0; c < 4; c++) acc[i][j][c] = 0.f;

    // ldmatrix base addresses
    int aRow = wr * 64 + (lane & 7) + ((lane >> 3) & 1) * 8;
    int aK   = (lane >> 4) * 8;
    int q2 = lane >> 3;
    int bRow = wc * 32 + ((q2 >> 1) * 8) + (lane & 7);
    int bK   = (q2 & 1) * 8;

    int buf = 0;
    for (int c = 0; c < DD / BK; c++) {
        if (c + 1 < DD / BK) {
            const __nv_bfloat16* gA = gA0 + (c + 1) * BK;
            const __nv_bfloat16* gB = gB0 + (c + 1) * BK;
            uint32_t dA = dstA0 + (buf ^ 1) * bufAbytes;
            uint32_t dB = dstB0 + (buf ^ 1) * bufAbytes;
            CP_ASYNC16(dA, gA);        CP_ASYNC16(dA + 32, gA + 16);
            CP_ASYNC16(dB, gB);        CP_ASYNC16(dB + 32, gB + 16);
            CP_COMMIT();
            asm volatile("cp.async.wait_group 1;" ::: "memory");
        } else {
            asm volatile("cp.async.wait_group 0;" ::: "memory");
        }
        __syncthreads();

        uint32_t aBase = sA + buf * bufAbytes;
        uint32_t bBase = sB + buf * bufAbytes;
        #pragma unroll
        for (int ks = 0; ks < 2; ks++) {
            uint32_t af[4][4];
            #pragma unroll
            for (int mt = 0; mt < 4; mt++) {
                uint32_t ad = aBase + ((aRow + mt * 16) * APAD + ks * 16 + aK) * 2;
                ldsm_x4(af[mt][0], af[mt][1], af[mt][2], af[mt][3], ad);
            }
            uint32_t bf[4][2];
            #pragma unroll
            for (int g = 0; g < 2; g++) {
                uint32_t bd = bBase + ((bRow + g * 16) * APAD + ks * 16 + bK) * 2;
                uint32_t t0, t1, t2, t3;
                ldsm_x4(t0, t1, t2, t3, bd);
                bf[g * 2][0] = t0;     bf[g * 2][1] = t1;
                bf[g * 2 + 1][0] = t2; bf[g * 2 + 1][1] = t3;
            }
            #pragma unroll
            for (int mt = 0; mt < 4; mt++)
                #pragma unroll
                for (int nt = 0; nt < 4; nt++)
                    mma16816(acc[mt][nt], af[mt][0], af[mt][1], af[mt][2], af[mt][3],
                             bf[nt][0], bf[nt][1]);
        }
        __syncthreads();
        buf ^= 1;
    }

    // epilogue: bias + mask + direct stores (float2 per fragment half)
    int colBase = n0 + wc * 32 + (lane & 3) * 2;
    int rowBase = m0 + wr * 64 + (lane >> 2);
    #pragma unroll
    for (int nt = 0; nt < 4; nt++) {
        int col = colBase + nt * 8;
        float bb0 = __ldg(bias + col), bb1 = __ldg(bias + col + 1);
        #pragma unroll
        for (int mt = 0; mt < 4; mt++) {
            int r1 = rowBase + mt * 16;
            int r2 = r1 + 8;
            float mk1 = mask[r1], mk2 = mask[r2];
            float add1 = (mat == 1) ? (1.0f - mk1) * NEGV : 0.0f;
            float add2 = (mat == 1) ? (1.0f - mk2) * NEGV : 0.0f;
            float mul1 = (mat == 2) ? mk1 : 1.0f;
            float mul2 = (mat == 2) ? mk2 : 1.0f;
            float2 o1 = { (acc[mt][nt][0] + bb0 + add1) * mul1,
                          (acc[mt][nt][1] + bb1 + add1) * mul1 };
            float2 o2 = { (acc[mt][nt][2] + bb0 + add2) * mul2,
                          (acc[mt][nt][3] + bb1 + add2) * mul2 };
            *(float2*)(C + (size_t)r1 * DD + col) = o1;
            *(float2*)(C + (size_t)r2 * DD + col) = o2;
        }
    }
}

// ---------------- zero att + Z ----------------
__global__ void zero_kernel() {
    int i = blockIdx.x * 256 + threadIdx.x;
    if (i < BB*HH*DH*DH) g_att[i] = 0.f;
    if (i < BB*DD)       g_Z[i]   = 0.f;
}

// ---------------- att = exp(K)^T V  (split over T, atomic accumulate), Z = col-sums of exp(K)
#define TSPLIT 16
__global__ __launch_bounds__(256) void att_kernel() {
    __shared__ float ks[16][132];
    __shared__ float vs[16][132];
    int tid = threadIdx.x;
    int bh = blockIdx.x;
    int b = bh >> 3, h = bh & 7;
    int n_start = blockIdx.y * (TT / TSPLIT);
    const float* kp = g_k + ((size_t)b * TT) * DD + h * DH;
    const float* vp = g_v + ((size_t)b * TT) * DD + h * DH;
    int tx = tid & 15, ty = tid >> 4;
    int lr = tid >> 4;
    int lc = (tid & 15) * 8;
    float acc[8][8];
    #pragma unroll
    for (int i = 0; i < 8; i++)
        #pragma unroll
        for (int j = 0; j < 8; j++) acc[i][j] = 0.f;
    float zacc = 0.f;

    for (int c = 0; c < TT / TSPLIT; c += 16) {
        size_t n = (size_t)(n_start + c + lr);
        const float* kr = kp + n * DD + lc;
        const float* vr = vp + n * DD + lc;
        float4 k0 = *(const float4*)kr, k1 = *(const float4*)(kr + 4);
        float4 v0 = *(const float4*)vr, v1 = *(const float4*)(vr + 4);
        float4 e0, e1;
        e0.x = __expf(k0.x); e0.y = __expf(k0.y); e0.z = __expf(k0.z); e0.w = __expf(k0.w);
        e1.x = __expf(k1.x); e1.y = __expf(k1.y); e1.z = __expf(k1.z); e1.w = __expf(k1.w);
        *(float4*)&ks[lr][lc]   = e0;
        *(float4*)&ks[lr][lc+4] = e1;
        *(float4*)&vs[lr][lc]   = v0;
        *(float4*)&vs[lr][lc+4] = v1;
        __syncthreads();
        if (tid < 128) {
            #pragma unroll
            for (int r = 0; r < 16; r++) zacc += ks[r][tid];
        }
        #pragma unroll
        for (int kk = 0; kk < 16; kk++) {
            float a[8], bf[8];
            *(float4*)(a)    = *(const float4*)&ks[kk][ty*8];
            *(float4*)(a+4)  = *(const float4*)&ks[kk][ty*8+4];
            *(float4*)(bf)   = *(const float4*)&vs[kk][tx*8];
            *(float4*)(bf+4) = *(const float4*)&vs[kk][tx*8+4];
            #pragma unroll
            for (int i = 0; i < 8; i++)
                #pragma unroll
                for (int j = 0; j < 8; j++)
                    acc[i][j] += a[i] * bf[j];
        }
        __syncthreads();
    }
    if (tid < 128) atomicAdd(&g_Z[b * DD + h * DH + tid], zacc);
    float* attp = g_att + (size_t)bh * DH * DH;
    #pragma unroll
    for (int i = 0; i < 8; i++)
        #pragma unroll
        for (int j = 0; j < 8; j++)
            atomicAdd(&attp[(ty*8+i)*DH + tx*8+j], acc[i][j]);
}

// ---------------- y = softmax_row(q) @ (att / Z) ; out = x + y ----------------
__global__ __launch_bounds__(256) void y_kernel(const float* __restrict__ x,
                                                float* __restrict__ out) {
    extern __shared__ float sm[];
    float* att_s = sm;
    float* qs    = sm + 128 * 132;
    int tid = threadIdx.x;
    int t0 = blockIdx.x * 128;
    int h = blockIdx.y;
    int b = blockIdx.z;
    int bh = b * HH + h;

    {
        const float* attp = g_att + (size_t)bh * DH * DH;
        int rr = tid >> 1;
        int part = (tid & 1) * 64;
        float zinv = 1.0f / g_Z[b * DD + h * DH + rr];
        #pragma unroll
        for (int c = 0; c < 64; c += 4) {
            float4 av = *(const float4*)(attp + rr * DH + part + c);
            av.x *= zinv; av.y *= zinv; av.z *= zinv; av.w *= zinv;
            *(float4*)&att_s[rr * 132 + part + c] = av;
        }
    }
    {
        int warp = tid >> 5, lane = tid & 31;
        for (int r = warp; r < 128; r += 8) {
            const float* qrow = g_q + ((size_t)(b * TT + t0 + r)) * DD + h * DH + lane * 4;
            float4 qv = *(const float4*)qrow;
            float mx = fmaxf(fmaxf(qv.x, qv.y), fmaxf(qv.z, qv.w));
            #pragma unroll
            for (int o = 16; o; o >>= 1) mx = fmaxf(mx, __shfl_xor_sync(0xffffffffu, mx, o));
            float e0 = __expf(qv.x - mx), e1 = __expf(qv.y - mx);
            float e2 = __expf(qv.z - mx), e3 = __expf(qv.w - mx);
            float s = e0 + e1 + e2 + e3;
            #pragma unroll
            for (int o = 16; o; o >>= 1) s += __shfl_xor_sync(0xffffffffu, s, o);
            float inv = 1.0f / s;
            float4 o4 = { e0*inv, e1*inv, e2*inv, e3*inv };
            *(float4*)&qs[r * 132 + lane * 4] = o4;
        }
    }
    __syncthreads();

    int tx = tid & 15, ty = tid >> 4;
    float acc[8][8];
    #pragma unroll
    for (int i = 0; i < 8; i++)
        #pragma unroll
        for (int j = 0; j < 8; j++) acc[i][j] = 0.f;

    for (int kk = 0; kk < DH; kk++) {
        float a[8], bf[8];
        #pragma unroll
        for (int i = 0; i < 8; i++) a[i] = qs[(ty*8+i) * 132 + kk];
        *(float4*)(bf)   = *(const float4*)&att_s[kk * 132 + tx*8];
        *(float4*)(bf+4) = *(const float4*)&att_s[kk * 132 + tx*8 + 4];
        #pragma unroll
        for (int i = 0; i < 8; i++)
            #pragma unroll
            for (int j = 0; j < 8; j++)
                acc[i][j] += a[i] * bf[j];
    }
    #pragma unroll
    for (int i = 0; i < 8; i++) {
        size_t base = ((size_t)(b * TT + t0 + ty*8 + i)) * DD + h * DH + tx * 8;
        float4 x0 = *(const float4*)(x + base);
        float4 x1 = *(const float4*)(x + base + 4);
        float4 o0 = { x0.x + acc[i][0], x0.y + acc[i][1], x0.z + acc[i][2], x0.w + acc[i][3] };
        float4 o1 = { x1.x + acc[i][4], x1.y + acc[i][5], x1.z + acc[i][6], x1.w + acc[i][7] };
        *(float4*)(out + base)     = o0;
        *(float4*)(out + base + 4) = o1;
    }
}

// ---------------- launch ----------------
extern "C" void kernel_launch(void* const* d_in, const int* in_sizes, int n_in,
                              void* d_out, int out_size) {
    const float* x        = (const float*)d_in[0];
    const float* src_mask = (const float*)d_in[1];
    const float* Wq       = (const float*)d_in[2];
    const float* bq       = (const float*)d_in[3];
    const float* Wk       = (const float*)d_in[4];
    const float* bk       = (const float*)d_in[5];
    const float* Wv       = (const float*)d_in[6];
    const float* bv       = (const float*)d_in[7];
    const float* gamma    = (const float*)d_in[8];
    const float* beta     = (const float*)d_in[9];
    float* out = (float*)d_out;

    int ysmem = 2 * 128 * 132 * 4;
    cudaFuncSetAttribute(y_kernel, cudaFuncAttributeMaxDynamicSharedMemorySize, ysmem);

    ln_kernel<<<MM, 256>>>(x, gamma, beta);
    wconv_kernel<<<dim3(32, 32, 3), dim3(32, 32)>>>(Wq, Wk, Wv);
    qkv_mma_kernel<<<dim3(DD / 128, MM / 128, 3), 256>>>(bq, bk, bv, src_mask);
    zero_kernel<<<(BB*HH*DH*DH + 255) / 256, 256>>>();
    att_kernel<<<dim3(BB*HH, TSPLIT), 256>>>();
    y_kernel<<<dim3(TT/128, HH, BB), 256, ysmem>>>(x, out);
}

// round 7
// speedup vs baseline: 4.2763x; 1.4979x over previous
#include <cuda_runtime.h>
#include <cuda_bf16.h>
#include <math.h>
#include <cstdint>

#define BB 4
#define TT 4096
#define DD 1024
#define HH 8
#define DH 128
#define MM (BB*TT)          // 16384 rows
#define NEGV (-1000000.0f)

// ---------------- scratch (static device allocations; no cudaMalloc) ----------------
__device__ __nv_bfloat16 g_xnb[(size_t)MM * DD];        // 32 MB  LayerNorm output (bf16)
__device__ __nv_bfloat16 g_wbT[3][(size_t)DD * DD];     // 6 MB   W transposed to [N][K] bf16
__device__ __nv_bfloat16 g_qb [(size_t)MM * DD];        // 32 MB  q (bf16, bias added)
__device__ __nv_bfloat16 g_ekb[(size_t)MM * DD];        // 32 MB  exp(k) (bf16; 0 on padded rows)
__device__ __nv_bfloat16 g_vb [(size_t)MM * DD];        // 32 MB  masked v (bf16)
__device__ float g_att[BB * HH * DH * DH];              // 2 MB   unnormalized att (atomic accum)
__device__ float g_Z [BB * DD];                         // time-softmax denominators

__device__ __forceinline__ uint32_t smem_u32(const void* p) {
    uint32_t a;
    asm("{ .reg .u64 t; cvta.to.shared.u64 t, %1; cvt.u32.u64 %0, t; }" : "=r"(a) : "l"(p));
    return a;
}
__device__ __forceinline__ void ldsm_x4(uint32_t& r0, uint32_t& r1, uint32_t& r2, uint32_t& r3, uint32_t a) {
    asm volatile("ldmatrix.sync.aligned.m8n8.x4.shared.b16 {%0,%1,%2,%3}, [%4];"
                 : "=r"(r0), "=r"(r1), "=r"(r2), "=r"(r3) : "r"(a));
}
__device__ __forceinline__ void ldsm_x4_t(uint32_t& r0, uint32_t& r1, uint32_t& r2, uint32_t& r3, uint32_t a) {
    asm volatile("ldmatrix.sync.aligned.m8n8.x4.trans.shared.b16 {%0,%1,%2,%3}, [%4];"
                 : "=r"(r0), "=r"(r1), "=r"(r2), "=r"(r3) : "r"(a));
}
__device__ __forceinline__ void mma16816(float* d, uint32_t a0, uint32_t a1, uint32_t a2, uint32_t a3,
                                         uint32_t b0, uint32_t b1) {
    asm volatile("mma.sync.aligned.m16n8k16.row.col.f32.bf16.bf16.f32 "
                 "{%0,%1,%2,%3}, {%4,%5,%6,%7}, {%8,%9}, {%0,%1,%2,%3};"
                 : "+f"(d[0]), "+f"(d[1]), "+f"(d[2]), "+f"(d[3])
                 : "r"(a0), "r"(a1), "r"(a2), "r"(a3), "r"(b0), "r"(b1));
}
#define CP_ASYNC16(sm, gm) asm volatile("cp.async.cg.shared.global [%0], [%1], 16;" :: "r"(sm), "l"(gm))
#define CP_COMMIT()        asm volatile("cp.async.commit_group;" ::: "memory")

// ---------------- LayerNorm -> bf16 xn ----------------
__global__ __launch_bounds__(256) void ln_kernel(const float* __restrict__ x,
                                                 const float* __restrict__ gamma,
                                                 const float* __restrict__ beta) {
    __shared__ float red[18];
    int row = blockIdx.x;
    int tid = threadIdx.x;
    const float4* xr = (const float4*)(x + (size_t)row * DD);
    float4 v = xr[tid];
    float s = v.x + v.y + v.z + v.w;
    #pragma unroll
    for (int o = 16; o; o >>= 1) s += __shfl_xor_sync(0xffffffffu, s, o);
    if ((tid & 31) == 0) red[tid >> 5] = s;
    __syncthreads();
    if (tid < 32) {
        float t = (tid < 8) ? red[tid] : 0.f;
        #pragma unroll
        for (int o = 4; o; o >>= 1) t += __shfl_xor_sync(0xffffffffu, t, o);
        if (tid == 0) red[16] = t;
    }
    __syncthreads();
    float mu = red[16] * (1.0f / DD);
    float d0 = v.x - mu, d1 = v.y - mu, d2 = v.z - mu, d3 = v.w - mu;
    float sq = d0*d0 + d1*d1 + d2*d2 + d3*d3;
    #pragma unroll
    for (int o = 16; o; o >>= 1) sq += __shfl_xor_sync(0xffffffffu, sq, o);
    if ((tid & 31) == 0) red[tid >> 5] = sq;
    __syncthreads();
    if (tid < 32) {
        float t = (tid < 8) ? red[tid] : 0.f;
        #pragma unroll
        for (int o = 4; o; o >>= 1) t += __shfl_xor_sync(0xffffffffu, t, o);
        if (tid == 0) red[17] = t;
    }
    __syncthreads();
    float inv = rsqrtf(red[17] * (1.0f / DD) + 1e-5f);
    float4 g  = ((const float4*)gamma)[tid];
    float4 bt = ((const float4*)beta)[tid];
    float o0 = d0 * inv * g.x + bt.x;
    float o1 = d1 * inv * g.y + bt.y;
    float o2 = d2 * inv * g.z + bt.z;
    float o3 = d3 * inv * g.w + bt.w;
    __nv_bfloat162* xo = (__nv_bfloat162*)(g_xnb + (size_t)row * DD);
    xo[tid * 2]     = __floats2bfloat162_rn(o0, o1);
    xo[tid * 2 + 1] = __floats2bfloat162_rn(o2, o3);
}

// ---------------- W -> bf16 transposed [N][K] ----------------
__global__ void wconv_kernel(const float* __restrict__ Wq,
                             const float* __restrict__ Wk,
                             const float* __restrict__ Wv) {
    __shared__ float t[32][33];
    int z = blockIdx.z;
    const float* W = (z == 0) ? Wq : (z == 1) ? Wk : Wv;
    int k = blockIdx.y * 32 + threadIdx.y;
    int n = blockIdx.x * 32 + threadIdx.x;
    t[threadIdx.y][threadIdx.x] = W[(size_t)k * DD + n];
    __syncthreads();
    int n2 = blockIdx.x * 32 + threadIdx.y;
    int k2 = blockIdx.y * 32 + threadIdx.x;
    g_wbT[z][(size_t)n2 * DD + k2] = __float2bfloat16_rn(t[threadIdx.x][threadIdx.y]);
}

// ================= QKV GEMM (mma.sync bf16, 3-stage cp.async) =================
#define BK 32
#define APAD 40
#define QBUF (128 * APAD)          // elements per stage per operand
#define QSMEM (3 * 2 * QBUF * 2)   // bytes

__global__ __launch_bounds__(256, 2) void qkv_mma_kernel(
    const float* __restrict__ bq, const float* __restrict__ bk,
    const float* __restrict__ bv, const float* __restrict__ mask) {
    extern __shared__ __nv_bfloat16 qsm[];
    __nv_bfloat16* As = qsm;               // 3 stages
    __nv_bfloat16* Bs = qsm + 3 * QBUF;
    int tid = threadIdx.x;
    int wid = tid >> 5, lane = tid & 31;
    int mat = blockIdx.z;
    int m0 = blockIdx.y * 128, n0 = blockIdx.x * 128;
    const __nv_bfloat16* Ag = g_xnb + (size_t)m0 * DD;
    const __nv_bfloat16* Bg = g_wbT[mat] + (size_t)n0 * DD;
    __nv_bfloat16* C = (mat == 0) ? g_qb : (mat == 1) ? g_ekb : g_vb;
    const float* bias = (mat == 0) ? bq : (mat == 1) ? bk : bv;

    // loader: row = tid>>1, chunks {u0, u0+2} of 4 x 16B per row
    int r0i = tid >> 1;
    int u0 = (tid & 1);
    uint32_t sA = smem_u32(As), sB = smem_u32(Bs);
    uint32_t dstA0 = sA + (r0i * APAD + u0 * 8) * 2;
    uint32_t dstB0 = sB + (r0i * APAD + u0 * 8) * 2;
    const __nv_bfloat16* gA0 = Ag + (size_t)r0i * DD + u0 * 8;
    const __nv_bfloat16* gB0 = Bg + (size_t)r0i * DD + u0 * 8;
    const uint32_t stageB = QBUF * 2;

    #define QLOAD(slot, c) {                                                  \
        uint32_t dA = dstA0 + (slot) * stageB;                                \
        uint32_t dB = dstB0 + (slot) * stageB;                                \
        const __nv_bfloat16* gA = gA0 + (c) * BK;                             \
        const __nv_bfloat16* gB = gB0 + (c) * BK;                             \
        CP_ASYNC16(dA, gA);        CP_ASYNC16(dA + 32, gA + 16);              \
        CP_ASYNC16(dB, gB);        CP_ASYNC16(dB + 32, gB + 16);              \
        CP_COMMIT(); }

    QLOAD(0, 0);
    QLOAD(1, 1);

    int wr = wid >> 2, wc = wid & 3;
    float acc[4][4][4];
    #pragma unroll
    for (int i = 0; i < 4; i++)
        #pragma unroll
        for (int j = 0; j < 4; j++)
            #pragma unroll
            for (int c = 0; c < 4; c++) acc[i][j][c] = 0.f;

    int aRow = (lane & 15);
    int aK   = (lane >> 4) * 8;
    int q2 = lane >> 3;
    int bRow = ((q2 >> 1) * 8) + (lane & 7);
    int bK   = (q2 & 1) * 8;

    for (int c = 0; c < DD / BK; c++) {
        if (c < DD / BK - 1) asm volatile("cp.async.wait_group 1;" ::: "memory");
        else                 asm volatile("cp.async.wait_group 0;" ::: "memory");
        __syncthreads();
        if (c + 2 < DD / BK) QLOAD((c + 2) % 3, c + 2);

        uint32_t aBase = sA + (c % 3) * stageB;
        uint32_t bBase = sB + (c % 3) * stageB;
        #pragma unroll
        for (int ks = 0; ks < 2; ks++) {
            uint32_t af[4][4];
            #pragma unroll
            for (int mt = 0; mt < 4; mt++) {
                uint32_t ad = aBase + ((wr * 64 + mt * 16 + aRow) * APAD + ks * 16 + aK) * 2;
                ldsm_x4(af[mt][0], af[mt][1], af[mt][2], af[mt][3], ad);
            }
            uint32_t bf[4][2];
            #pragma unroll
            for (int g = 0; g < 2; g++) {
                uint32_t bd = bBase + ((wc * 32 + g * 16 + bRow) * APAD + ks * 16 + bK) * 2;
                uint32_t t0, t1, t2, t3;
                ldsm_x4(t0, t1, t2, t3, bd);
                bf[g * 2][0] = t0;     bf[g * 2][1] = t1;
                bf[g * 2 + 1][0] = t2; bf[g * 2 + 1][1] = t3;
            }
            #pragma unroll
            for (int mt = 0; mt < 4; mt++)
                #pragma unroll
                for (int nt = 0; nt < 4; nt++)
                    mma16816(acc[mt][nt], af[mt][0], af[mt][1], af[mt][2], af[mt][3],
                             bf[nt][0], bf[nt][1]);
        }
    }

    // epilogue: bias + transform + bf16 stores
    int colBase = n0 + wc * 32 + (lane & 3) * 2;
    int rowBase = m0 + wr * 64 + (lane >> 2);
    #pragma unroll
    for (int nt = 0; nt < 4; nt++) {
        int col = colBase + nt * 8;
        float bb0 = __ldg(bias + col), bb1 = __ldg(bias + col + 1);
        #pragma unroll
        for (int mt = 0; mt < 4; mt++) {
            int r1 = rowBase + mt * 16;
            int r2 = r1 + 8;
            float mk1 = mask[r1], mk2 = mask[r2];
            float v0 = acc[mt][nt][0] + bb0, v1 = acc[mt][nt][1] + bb1;
            float v2 = acc[mt][nt][2] + bb0, v3 = acc[mt][nt][3] + bb1;
            if (mat == 1) {
                float a1 = (1.0f - mk1) * NEGV, a2 = (1.0f - mk2) * NEGV;
                v0 = __expf(v0 + a1); v1 = __expf(v1 + a1);
                v2 = __expf(v2 + a2); v3 = __expf(v3 + a2);
            } else if (mat == 2) {
                v0 *= mk1; v1 *= mk1; v2 *= mk2; v3 *= mk2;
            }
            *(__nv_bfloat162*)(C + (size_t)r1 * DD + col) = __floats2bfloat162_rn(v0, v1);
            *(__nv_bfloat162*)(C + (size_t)r2 * DD + col) = __floats2bfloat162_rn(v2, v3);
        }
    }
}

// ---------------- zero att + Z ----------------
__global__ void zero_kernel() {
    int i = blockIdx.x * 256 + threadIdx.x;
    if (i < BB*HH*DH*DH) g_att[i] = 0.f;
    if (i < BB*DD)       g_Z[i]   = 0.f;
}

// ---------------- Z = column sums of ek over time ----------------
__global__ __launch_bounds__(256) void z_kernel() {
    int b = blockIdx.x;
    int d = blockIdx.y * 256 + threadIdx.x;
    int t0 = blockIdx.z * (TT / 8);
    const __nv_bfloat16* p = g_ekb + ((size_t)(b * TT + t0)) * DD + d;
    float s = 0.f;
    #pragma unroll 8
    for (int t = 0; t < TT / 8; t++) s += __bfloat162float(p[(size_t)t * DD]);
    atomicAdd(&g_Z[b * DD + d], s);
}

// ---------------- att = ek^T v via mma (trans ldmatrix both operands) ----------------
#define ATSPLIT 8
#define EPAD 136
__global__ __launch_bounds__(256) void att_mma_kernel() {
    __shared__ __nv_bfloat16 eks[2][32 * EPAD];
    __shared__ __nv_bfloat16 vs [2][32 * EPAD];
    int tid = threadIdx.x;
    int wid = tid >> 5, lane = tid & 31;
    int bh = blockIdx.x;
    int b = bh >> 3, h = bh & 7;
    int tstart = blockIdx.y * (TT / ATSPLIT);   // 512 timesteps per block
    const __nv_bfloat16* ekg = g_ekb + ((size_t)(b * TT + tstart)) * DD + h * DH;
    const __nv_bfloat16* vg  = g_vb  + ((size_t)(b * TT + tstart)) * DD + h * DH;

    uint32_t sE = smem_u32(eks), sV = smem_u32(vs);
    // loader: 512 16B-chunks per operand per 32-row chunk; 2 per thread
    int lrow0 = tid >> 4, lc0 = (tid & 15);           // idx = tid
    int lrow1 = (tid + 256) >> 4, lc1 = (tid & 15);   // idx = tid+256

    #define ALOAD(buf, c) {                                                              \
        size_t roff0 = (size_t)((c) * 32 + lrow0) * DD + lc0 * 8;                        \
        size_t roff1 = (size_t)((c) * 32 + lrow1) * DD + lc1 * 8;                        \
        uint32_t d0 = (buf) * 32 * EPAD * 2 + (lrow0 * EPAD + lc0 * 8) * 2;              \
        uint32_t d1 = (buf) * 32 * EPAD * 2 + (lrow1 * EPAD + lc1 * 8) * 2;              \
        CP_ASYNC16(sE + d0, ekg + roff0);  CP_ASYNC16(sE + d1, ekg + roff1);             \
        CP_ASYNC16(sV + d0, vg  + roff0);  CP_ASYNC16(sV + d1, vg  + roff1);             \
        CP_COMMIT(); }

    ALOAD(0, 0);

    int wr = wid >> 2, wc = wid & 3;
    float acc[4][4][4];
    #pragma unroll
    for (int i = 0; i < 4; i++)
        #pragma unroll
        for (int j = 0; j < 4; j++)
            #pragma unroll
            for (int c = 0; c < 4; c++) acc[i][j][c] = 0.f;

    int rowf = ((lane >> 4) & 1) * 8 + (lane & 7);
    int colf = ((lane >> 3) & 1) * 8;

    int buf = 0;
    const int NC = (TT / ATSPLIT) / 32;   // 16 chunks
    for (int c = 0; c < NC; c++) {
        if (c + 1 < NC) {
            ALOAD(buf ^ 1, c + 1);
            asm volatile("cp.async.wait_group 1;" ::: "memory");
        } else {
            asm volatile("cp.async.wait_group 0;" ::: "memory");
        }
        __syncthreads();

        uint32_t eBase = sE + buf * 32 * EPAD * 2;
        uint32_t vBase = sV + buf * 32 * EPAD * 2;
        #pragma unroll
        for (int ks = 0; ks < 2; ks++) {
            uint32_t af[4][4];
            #pragma unroll
            for (int mt = 0; mt < 4; mt++) {
                uint32_t ad = eBase + ((ks * 16 + rowf) * EPAD + wr * 64 + mt * 16 + colf) * 2;
                ldsm_x4_t(af[mt][0], af[mt][1], af[mt][2], af[mt][3], ad);
            }
            uint32_t bf[4][2];
            #pragma unroll
            for (int g = 0; g < 2; g++) {
                uint32_t bd = vBase + ((ks * 16 + rowf) * EPAD + wc * 32 + g * 16 + colf) * 2;
                uint32_t t0, t1, t2, t3;
                ldsm_x4_t(t0, t1, t2, t3, bd);
                bf[g * 2][0] = t0;     bf[g * 2][1] = t2;   // n-tile0: (k0,n0),(k8,n0)
                bf[g * 2 + 1][0] = t1; bf[g * 2 + 1][1] = t3; // n-tile1
            }
            #pragma unroll
            for (int mt = 0; mt < 4; mt++)
                #pragma unroll
                for (int nt = 0; nt < 4; nt++)
                    mma16816(acc[mt][nt], af[mt][0], af[mt][1], af[mt][2], af[mt][3],
                             bf[nt][0], bf[nt][1]);
        }
        __syncthreads();
        buf ^= 1;
    }

    float* attp = g_att + (size_t)bh * DH * DH;
    int dr = wr * 64 + (lane >> 2);
    int lcb = wc * 32 + (lane & 3) * 2;
    #pragma unroll
    for (int mt = 0; mt < 4; mt++)
        #pragma unroll
        for (int nt = 0; nt < 4; nt++) {
            int d1 = dr + mt * 16, l0 = lcb + nt * 8;
            atomicAdd(&attp[d1 * DH + l0],       acc[mt][nt][0]);
            atomicAdd(&attp[d1 * DH + l0 + 1],   acc[mt][nt][1]);
            atomicAdd(&attp[(d1+8) * DH + l0],   acc[mt][nt][2]);
            atomicAdd(&attp[(d1+8) * DH + l0+1], acc[mt][nt][3]);
        }
}

// ---------------- y = softmax_row(q) @ (att/Z) via mma ; out = x + y ----------------
#define YSMEM (2 * 128 * EPAD * 2)
__global__ __launch_bounds__(256) void y_mma_kernel(const float* __restrict__ x,
                                                    float* __restrict__ out) {
    extern __shared__ __nv_bfloat16 ysm[];
    __nv_bfloat16* att_s = ysm;               // [128][EPAD]
    __nv_bfloat16* qs    = ysm + 128 * EPAD;  // [128][EPAD]
    int tid = threadIdx.x;
    int wid = tid >> 5, lane = tid & 31;
    int t0 = blockIdx.x * 128;
    int h = blockIdx.y;
    int b = blockIdx.z;
    int bh = b * HH + h;

    // att -> normalized bf16 in smem
    {
        int d = tid >> 1;
        int lp = (tid & 1) * 64;
        float zinv = 1.0f / g_Z[b * DD + h * DH + d];
        const float* ap = g_att + (size_t)bh * DH * DH + d * DH + lp;
        __nv_bfloat162* dst = (__nv_bfloat162*)(att_s + d * EPAD + lp);
        #pragma unroll
        for (int c = 0; c < 64; c += 4) {
            float4 av = *(const float4*)(ap + c);
            dst[c/2]   = __floats2bfloat162_rn(av.x * zinv, av.y * zinv);
            dst[c/2+1] = __floats2bfloat162_rn(av.z * zinv, av.w * zinv);
        }
    }
    // q softmax -> bf16 smem
    for (int r = wid; r < 128; r += 8) {
        const __nv_bfloat16* qrow = g_qb + ((size_t)(b * TT + t0 + r)) * DD + h * DH + lane * 4;
        uint2 u = *(const uint2*)qrow;
        __nv_bfloat162 p0 = *(__nv_bfloat162*)&u.x;
        __nv_bfloat162 p1 = *(__nv_bfloat162*)&u.y;
        float q0 = __bfloat162float(p0.x), q1 = __bfloat162float(p0.y);
        float q2 = __bfloat162float(p1.x), q3 = __bfloat162float(p1.y);
        float mx = fmaxf(fmaxf(q0, q1), fmaxf(q2, q3));
        #pragma unroll
        for (int o = 16; o; o >>= 1) mx = fmaxf(mx, __shfl_xor_sync(0xffffffffu, mx, o));
        float e0 = __expf(q0 - mx), e1 = __expf(q1 - mx);
        float e2 = __expf(q2 - mx), e3 = __expf(q3 - mx);
        float s = e0 + e1 + e2 + e3;
        #pragma unroll
        for (int o = 16; o; o >>= 1) s += __shfl_xor_sync(0xffffffffu, s, o);
        float inv = 1.0f / s;
        __nv_bfloat162* dst = (__nv_bfloat162*)(qs + r * EPAD + lane * 4);
        dst[0] = __floats2bfloat162_rn(e0 * inv, e1 * inv);
        dst[1] = __floats2bfloat162_rn(e2 * inv, e3 * inv);
    }
    __syncthreads();

    uint32_t sQ = smem_u32(qs), sAt = smem_u32(att_s);
    int wr = wid >> 2, wc = wid & 3;
    float acc[4][4][4];
    #pragma unroll
    for (int i = 0; i < 4; i++)
        #pragma unroll
        for (int j = 0; j < 4; j++)
            #pragma unroll
            for (int c = 0; c < 4; c++) acc[i][j][c] = 0.f;

    int aRow = (lane & 15);
    int aK   = (lane >> 4) * 8;
    int rowf = ((lane >> 4) & 1) * 8 + (lane & 7);
    int colf = ((lane >> 3) & 1) * 8;

    #pragma unroll
    for (int ks = 0; ks < 8; ks++) {
        uint32_t af[4][4];
        #pragma unroll
        for (int mt = 0; mt < 4; mt++) {
            uint32_t ad = sQ + ((wr * 64 + mt * 16 + aRow) * EPAD + ks * 16 + aK) * 2;
            ldsm_x4(af[mt][0], af[mt][1], af[mt][2], af[mt][3], ad);
        }
        uint32_t bf[4][2];
        #pragma unroll
        for (int g = 0; g < 2; g++) {
            uint32_t bd = sAt + ((ks * 16 + rowf) * EPAD + wc * 32 + g * 16 + colf) * 2;
            uint32_t u0, u1, u2, u3;
            ldsm_x4_t(u0, u1, u2, u3, bd);
            bf[g * 2][0] = u0;     bf[g * 2][1] = u2;
            bf[g * 2 + 1][0] = u1; bf[g * 2 + 1][1] = u3;
        }
        #pragma unroll
        for (int mt = 0; mt < 4; mt++)
            #pragma unroll
            for (int nt = 0; nt < 4; nt++)
                mma16816(acc[mt][nt], af[mt][0], af[mt][1], af[mt][2], af[mt][3],
                         bf[nt][0], bf[nt][1]);
    }

    int rb = wr * 64 + (lane >> 2);
    int cb = h * DH + wc * 32 + (lane & 3) * 2;
    #pragma unroll
    for (int mt = 0; mt < 4; mt++) {
        int r1 = t0 + rb + mt * 16;
        int r2 = r1 + 8;
        #pragma unroll
        for (int nt = 0; nt < 4; nt++) {
            size_t base1 = (size_t)(b * TT + r1) * DD + cb + nt * 8;
            size_t base2 = (size_t)(b * TT + r2) * DD + cb + nt * 8;
            float2 x1 = *(const float2*)(x + base1);
            float2 x2 = *(const float2*)(x + base2);
            float2 o1 = { x1.x + acc[mt][nt][0], x1.y + acc[mt][nt][1] };
            float2 o2 = { x2.x + acc[mt][nt][2], x2.y + acc[mt][nt][3] };
            *(float2*)(out + base1) = o1;
            *(float2*)(out + base2) = o2;
        }
    }
}

// ---------------- launch ----------------
extern "C" void kernel_launch(void* const* d_in, const int* in_sizes, int n_in,
                              void* d_out, int out_size) {
    const float* x        = (const float*)d_in[0];
    const float* src_mask = (const float*)d_in[1];
    const float* Wq       = (const float*)d_in[2];
    const float* bq       = (const float*)d_in[3];
    const float* Wk       = (const float*)d_in[4];
    const float* bk       = (const float*)d_in[5];
    const float* Wv       = (const float*)d_in[6];
    const float* bv       = (const float*)d_in[7];
    const float* gamma    = (const float*)d_in[8];
    const float* beta     = (const float*)d_in[9];
    float* out = (float*)d_out;

    cudaFuncSetAttribute(qkv_mma_kernel, cudaFuncAttributeMaxDynamicSharedMemorySize, QSMEM);
    cudaFuncSetAttribute(y_mma_kernel,  cudaFuncAttributeMaxDynamicSharedMemorySize, YSMEM);

    ln_kernel<<<MM, 256>>>(x, gamma, beta);
    wconv_kernel<<<dim3(32, 32, 3), dim3(32, 32)>>>(Wq, Wk, Wv);
    qkv_mma_kernel<<<dim3(DD / 128, MM / 128, 3), 256, QSMEM>>>(bq, bk, bv, src_mask);
    zero_kernel<<<(BB*HH*DH*DH + 255) / 256, 256>>>();
    z_kernel<<<dim3(BB, DD / 256, 8), 256>>>();
    att_mma_kernel<<<dim3(BB*HH, ATSPLIT), 256>>>();
    y_mma_kernel<<<dim3(TT/128, HH, BB), 256, YSMEM>>>(x, out);
}